// round 7
// baseline (speedup 1.0000x reference)
#include <cuda_runtime.h>
#include <math.h>

typedef unsigned long long ull;

// Problem constants
#define BMT 32      // B*M
#define NN 1024     // nodes
#define DD 128      // input dim
#define PP 64       // projection dim
#define NC 10       // clusters
#define FF 128      // output features
#define KK 10       // k neighbors
#define INV_SQRT11 0.30151134457776363f

// kNN tiling
#define ROWT 64
#define COLT 32
#define NKP2 (PP / 4)   // 16 quads of 4 floats (2 f32x2 pairs)

// ---------------- scratch (device globals: allocation-free) ----------------
__device__ ull   g_Zt[BMT * NKP2 * NN * 2];  // Z transposed: (bm, kp2, row) -> ull2 (4 floats)
__device__ float g_sq[BMT * NN];             // squared norms
__device__ int   g_idx[BMT * NN * KK];       // knn indices
__device__ float g_Hc[BMT * NN * NC];        // cluster softmax probs
__device__ float g_Xs[BMT * NN * FF];        // X_trans * 1/sqrt(11)
__device__ int   g_cnt[BMT * NN];            // per-edge degree of H_knn
__device__ int   g_start[BMT * NN];          // CSR starts
__device__ int   g_fill[BMT * NN];           // CSR fill cursors
__device__ int   g_list[BMT * NN * KK];      // CSR column lists
__device__ float g_tmpE[BMT * NN * FF];      // De_inv * (H_knn^T @ Xs)
__device__ float g_tmpC[BMT * NC * FF];      // H_cluster^T @ Xs (unscaled)
__device__ float g_DeC[BMT * NC];            // cluster edge degrees

// ---------------- f32x2 helpers ----------------
__device__ __forceinline__ void fma2(ull& d, ull a, ull b) {
    asm("fma.rn.f32x2 %0, %1, %2, %3;" : "=l"(d) : "l"(a), "l"(b), "l"(d));
}
__device__ __forceinline__ ull pack2(float lo, float hi) {
    ull d;
    asm("mov.b64 %0, {%1, %2};" : "=l"(d) : "r"(__float_as_uint(lo)), "r"(__float_as_uint(hi)));
    return d;
}
__device__ __forceinline__ void unpack2(ull v, float& lo, float& hi) {
    unsigned a, b;
    asm("mov.b64 {%0, %1}, %2;" : "=r"(a), "=r"(b) : "l"(v));
    lo = __uint_as_float(a);
    hi = __uint_as_float(b);
}
__device__ __forceinline__ void cpa16(unsigned s, const void* g) {
    asm volatile("cp.async.cg.shared.global [%0], [%1], 16;" :: "r"(s), "l"(g));
}

// ---------------- merged GEMM: Z (z<2) and Xs (z>=2) in one kernel ----------
// Tile: 64 rows x 32 cols, 128 threads, thread tile 4x4 (16 f32x2 accs).
// z in [0,6): z<2 -> Z cols z*32 (transposed pair-packed to g_Zt),
//             z>=2 -> Xs cols (z-2)*32 (row-major to g_Xs).
__global__ void __launch_bounds__(128, 6) k_gemm(const float* __restrict__ X,
                                                 const float* __restrict__ Wp,
                                                 const float* __restrict__ Wpb,
                                                 const float* __restrict__ Tw,
                                                 const float* __restrict__ Tb) {
    __shared__ __align__(16) char smem_raw[24576];
    ulonglong2* sAp = (ulonglong2*)smem_raw;            // [2][8][64] = 16 KB
    ulonglong2* sWp = (ulonglong2*)(smem_raw + 16384);  // [2][8][32] = 8 KB

    int bm = blockIdx.x;
    int row0 = blockIdx.y * 64;
    int z = blockIdx.z;
    int b = bm >> 3, m = bm & 7;
    int tid = threadIdx.x;
    if (bm == 0 && blockIdx.y == 0 && z == 0) {
        for (int i = tid; i < BMT * NC; i += 128) g_DeC[i] = 0.f;
    }
    const float* Wsel = (z < 2) ? Wp : Tw;
    const float* Bsel = (z < 2) ? Wpb : Tb;
    int colbase = (z < 2) ? z * 32 : (z - 2) * 32;
    float scale = (z < 2) ? 1.0f : INV_SQRT11;

    const float* xbase = X + ((size_t)(b * NN) * 8 + m) * DD;
    unsigned sA_u = (unsigned)__cvta_generic_to_shared(sAp);
    unsigned sW_u = (unsigned)__cvta_generic_to_shared(sWp);

    auto issue = [&](int ch) {
        int st = ch & 1;
        // A: 8 kp2 x 64 rows = 512 ull2; 4 per thread
#pragma unroll
        for (int q = 0; q < 4; q++) {
            int e = tid + q * 128;
            int kp2 = e >> 6, r = e & 63;
            unsigned sa = sA_u + ((st * 8 + kp2) * 64 + r) * 16;
            cpa16(sa, xbase + (size_t)(row0 + r) * 1024 + ch * 32 + kp2 * 4);
        }
        // W: 8 kp2 x 32 cols = 256 ull2; 2 per thread
#pragma unroll
        for (int q = 0; q < 2; q++) {
            int e = tid + q * 128;
            int kp2 = e >> 5, c = e & 31;
            unsigned sw = sW_u + ((st * 8 + kp2) * 32 + c) * 16;
            cpa16(sw, Wsel + (size_t)(colbase + c) * DD + ch * 32 + kp2 * 4);
        }
        asm volatile("cp.async.commit_group;");
    };

    int tr = tid >> 3;  // 0..15 -> rows tr + 16*i
    int tc = tid & 7;   // 0..7  -> cols tc + 8*j

    ull acc[4][4] = {};

    issue(0);
#pragma unroll
    for (int ch = 0; ch < 4; ch++) {
        if (ch < 3) {
            issue(ch + 1);
            asm volatile("cp.async.wait_group 1;");
        } else {
            asm volatile("cp.async.wait_group 0;");
        }
        __syncthreads();
        int st = ch & 1;
#pragma unroll
        for (int kp2 = 0; kp2 < 8; kp2++) {
            const ulonglong2* ab = sAp + (st * 8 + kp2) * 64;
            const ulonglong2* wb = sWp + (st * 8 + kp2) * 32;
            ulonglong2 a0 = ab[tr + 0];
            ulonglong2 a1 = ab[tr + 16];
            ulonglong2 a2 = ab[tr + 32];
            ulonglong2 a3 = ab[tr + 48];
            ulonglong2 w0 = wb[tc + 0];
            ulonglong2 w1 = wb[tc + 8];
            ulonglong2 w2 = wb[tc + 16];
            ulonglong2 w3 = wb[tc + 24];
            fma2(acc[0][0], a0.x, w0.x); fma2(acc[0][0], a0.y, w0.y);
            fma2(acc[0][1], a0.x, w1.x); fma2(acc[0][1], a0.y, w1.y);
            fma2(acc[0][2], a0.x, w2.x); fma2(acc[0][2], a0.y, w2.y);
            fma2(acc[0][3], a0.x, w3.x); fma2(acc[0][3], a0.y, w3.y);
            fma2(acc[1][0], a1.x, w0.x); fma2(acc[1][0], a1.y, w0.y);
            fma2(acc[1][1], a1.x, w1.x); fma2(acc[1][1], a1.y, w1.y);
            fma2(acc[1][2], a1.x, w2.x); fma2(acc[1][2], a1.y, w2.y);
            fma2(acc[1][3], a1.x, w3.x); fma2(acc[1][3], a1.y, w3.y);
            fma2(acc[2][0], a2.x, w0.x); fma2(acc[2][0], a2.y, w0.y);
            fma2(acc[2][1], a2.x, w1.x); fma2(acc[2][1], a2.y, w1.y);
            fma2(acc[2][2], a2.x, w2.x); fma2(acc[2][2], a2.y, w2.y);
            fma2(acc[2][3], a2.x, w3.x); fma2(acc[2][3], a2.y, w3.y);
            fma2(acc[3][0], a3.x, w0.x); fma2(acc[3][0], a3.y, w0.y);
            fma2(acc[3][1], a3.x, w1.x); fma2(acc[3][1], a3.y, w1.y);
            fma2(acc[3][2], a3.x, w2.x); fma2(acc[3][2], a3.y, w2.y);
            fma2(acc[3][3], a3.x, w3.x); fma2(acc[3][3], a3.y, w3.y);
        }
        __syncthreads();
    }

    float bv[4];
#pragma unroll
    for (int j = 0; j < 4; j++) bv[j] = Bsel[colbase + tc + 8 * j];

    if (z >= 2) {
#pragma unroll
        for (int i = 0; i < 4; i++) {
            int n = row0 + tr + 16 * i;
            float* op = g_Xs + ((size_t)bm * NN + n) * FF + colbase;
#pragma unroll
            for (int j = 0; j < 4; j++) {
                float lo, hi;
                unpack2(acc[i][j], lo, hi);
                op[tc + 8 * j] = (lo + hi + bv[j]) * scale;
            }
        }
    } else {
        // transpose epilogue into g_Zt; sT[col][row], 66-float pad
        float* sT = (float*)smem_raw;  // 32*66*4 = 8.25 KB
#pragma unroll
        for (int i = 0; i < 4; i++) {
            int r = tr + 16 * i;
#pragma unroll
            for (int j = 0; j < 4; j++) {
                float lo, hi;
                unpack2(acc[i][j], lo, hi);
                sT[(tc + 8 * j) * 66 + r] = lo + hi + bv[j];
            }
        }
        __syncthreads();
        ulonglong2* zt2 = (ulonglong2*)g_Zt;
#pragma unroll
        for (int q = 0; q < 4; q++) {
            int e = tid + q * 128;
            int kp2l = e >> 6, r = e & 63;
            float z0 = sT[(kp2l * 4 + 0) * 66 + r];
            float z1 = sT[(kp2l * 4 + 1) * 66 + r];
            float z2 = sT[(kp2l * 4 + 2) * 66 + r];
            float z3 = sT[(kp2l * 4 + 3) * 66 + r];
            ulonglong2 v;
            v.x = pack2(z0, z1);
            v.y = pack2(z2, z3);
            zt2[((size_t)(bm * NKP2 + z * 8 + kp2l)) * NN + row0 + r] = v;
        }
    }
}

// ---------------- K_cluster_sq: softmax + DeC + sq norm + zero cnt/tmpC ----
__global__ void __launch_bounds__(256) k_cluster_sq(const float* __restrict__ C) {
    __shared__ float sC[NC * PP];
    __shared__ float sDeC[NC];
    int tid = threadIdx.x;
    for (int t = tid; t < NC * PP; t += 256) sC[t] = C[t];
    if (tid < NC) sDeC[tid] = 0.f;
    __syncthreads();
    int row = blockIdx.x * 256 + tid;
    int bm = row >> 10;
    int n = row & (NN - 1);
    g_cnt[row] = 0;
    for (int i = row; i < BMT * NC * FF; i += BMT * NN) g_tmpC[i] = 0.f;
    const ulonglong2* zt2 = (const ulonglong2*)g_Zt;
    float acc[NC] = {};
    float sq = 0.f;
#pragma unroll
    for (int kp2 = 0; kp2 < NKP2; kp2++) {
        ulonglong2 v = zt2[((size_t)(bm * NKP2 + kp2)) * NN + n];
        float z0, z1, z2, z3;
        unpack2(v.x, z0, z1);
        unpack2(v.y, z2, z3);
        sq = fmaf(z0, z0, fmaf(z1, z1, fmaf(z2, z2, fmaf(z3, z3, sq))));
        const float* cp = &sC[kp2 * 4];
#pragma unroll
        for (int c = 0; c < NC; c++) {
            acc[c] = fmaf(z0, cp[c * PP + 0], acc[c]);
            acc[c] = fmaf(z1, cp[c * PP + 1], acc[c]);
            acc[c] = fmaf(z2, cp[c * PP + 2], acc[c]);
            acc[c] = fmaf(z3, cp[c * PP + 3], acc[c]);
        }
    }
    g_sq[row] = sq;
    float mx = acc[0];
#pragma unroll
    for (int c = 1; c < NC; c++) mx = fmaxf(mx, acc[c]);
    float p[NC], sum = 0.f;
#pragma unroll
    for (int c = 0; c < NC; c++) {
        p[c] = expf(acc[c] - mx);
        sum += p[c];
    }
    float inv = 1.f / sum;
#pragma unroll
    for (int c = 0; c < NC; c++) {
        p[c] *= inv;
        g_Hc[(size_t)row * NC + c] = p[c];
    }
#pragma unroll
    for (int c = 0; c < NC; c++)
#pragma unroll
        for (int o = 16; o; o >>= 1) p[c] += __shfl_xor_sync(0xffffffffu, p[c], o);
    if ((tid & 31) == 0) {
#pragma unroll
        for (int c = 0; c < NC; c++) atomicAdd(&sDeC[c], p[c]);
    }
    __syncthreads();
    if (tid < NC) atomicAdd(&g_DeC[bm * NC + tid], sDeC[tid]);
}

// ---------------- K2: FMA2-bound Gram tiles + in-kernel top-10 ----------------
__global__ void __launch_bounds__(128) k_knn() {
    int bm = blockIdx.y;
    int row0 = blockIdx.x * ROWT;

    __shared__ __align__(16) ulonglong2 sQ[NKP2][ROWT];  // 16KB
    __shared__ __align__(16) ulonglong2 sK[NKP2][COLT];  // 8KB
    __shared__ float sD[COLT][ROWT + 2];                 // 8.25KB
    __shared__ float ssq[COLT];
    __shared__ float sMv[ROWT][KK];
    __shared__ int   sMi[ROWT][KK];

    const ulonglong2* zt2 = (const ulonglong2*)g_Zt + (size_t)bm * NKP2 * NN;
    int tid = threadIdx.x;

#pragma unroll
    for (int e = tid; e < NKP2 * ROWT; e += 128) {
        int kp2 = e >> 6, r = e & 63;
        sQ[kp2][r] = zt2[(size_t)kp2 * NN + row0 + r];
    }

    int tr = tid >> 3;
    int tc = tid & 7;
    int myrow = tid & 63;
    int half = tid >> 6;

    float vals[KK];
    int idxs[KK];
#pragma unroll
    for (int k = 0; k < KK; k++) {
        vals[k] = __int_as_float(0x7f800000);
        idxs[k] = 0x7fffffff;
    }

    for (int j0 = 0; j0 < NN; j0 += COLT) {
#pragma unroll
        for (int e = tid; e < NKP2 * COLT; e += 128) {
            int kp2 = e >> 5, r = e & 31;
            sK[kp2][r] = zt2[(size_t)kp2 * NN + j0 + r];
        }
        if (tid < COLT) ssq[tid] = g_sq[bm * NN + j0 + tid];
        __syncthreads();

        ull acc[4][4] = {};
#pragma unroll
        for (int kp2 = 0; kp2 < NKP2; kp2++) {
            ulonglong2 q0 = sQ[kp2][tr + 0];
            ulonglong2 q1 = sQ[kp2][tr + 16];
            ulonglong2 q2 = sQ[kp2][tr + 32];
            ulonglong2 q3 = sQ[kp2][tr + 48];
            ulonglong2 c0 = sK[kp2][tc + 0];
            ulonglong2 c1 = sK[kp2][tc + 8];
            ulonglong2 c2 = sK[kp2][tc + 16];
            ulonglong2 c3 = sK[kp2][tc + 24];
            fma2(acc[0][0], q0.x, c0.x); fma2(acc[0][0], q0.y, c0.y);
            fma2(acc[0][1], q0.x, c1.x); fma2(acc[0][1], q0.y, c1.y);
            fma2(acc[0][2], q0.x, c2.x); fma2(acc[0][2], q0.y, c2.y);
            fma2(acc[0][3], q0.x, c3.x); fma2(acc[0][3], q0.y, c3.y);
            fma2(acc[1][0], q1.x, c0.x); fma2(acc[1][0], q1.y, c0.y);
            fma2(acc[1][1], q1.x, c1.x); fma2(acc[1][1], q1.y, c1.y);
            fma2(acc[1][2], q1.x, c2.x); fma2(acc[1][2], q1.y, c2.y);
            fma2(acc[1][3], q1.x, c3.x); fma2(acc[1][3], q1.y, c3.y);
            fma2(acc[2][0], q2.x, c0.x); fma2(acc[2][0], q2.y, c0.y);
            fma2(acc[2][1], q2.x, c1.x); fma2(acc[2][1], q2.y, c1.y);
            fma2(acc[2][2], q2.x, c2.x); fma2(acc[2][2], q2.y, c2.y);
            fma2(acc[2][3], q2.x, c3.x); fma2(acc[2][3], q2.y, c3.y);
            fma2(acc[3][0], q3.x, c0.x); fma2(acc[3][0], q3.y, c0.y);
            fma2(acc[3][1], q3.x, c1.x); fma2(acc[3][1], q3.y, c1.y);
            fma2(acc[3][2], q3.x, c2.x); fma2(acc[3][2], q3.y, c2.y);
            fma2(acc[3][3], q3.x, c3.x); fma2(acc[3][3], q3.y, c3.y);
        }
#pragma unroll
        for (int i = 0; i < 4; i++) {
#pragma unroll
            for (int j = 0; j < 4; j++) {
                float lo, hi;
                unpack2(acc[i][j], lo, hi);
                int col = tc + 8 * j;
                sD[col][tr + 16 * i] = fmaf(-2.f, lo + hi, ssq[col]);
            }
        }
        __syncthreads();

        int cb = half * 16;
#pragma unroll
        for (int cc = 0; cc < 16; cc++) {
            float d2 = sD[cb + cc][myrow];
            if (d2 < vals[KK - 1]) {
                vals[KK - 1] = d2;
                idxs[KK - 1] = j0 + cb + cc;
#pragma unroll
                for (int p = KK - 1; p > 0; --p) {
                    bool s = vals[p] < vals[p - 1];
                    float va = vals[p - 1];
                    int ia = idxs[p - 1];
                    vals[p - 1] = s ? vals[p] : va;
                    idxs[p - 1] = s ? idxs[p] : ia;
                    vals[p] = s ? va : vals[p];
                    idxs[p] = s ? ia : idxs[p];
                }
            }
        }
        __syncthreads();
    }

    if (half == 1) {
#pragma unroll
        for (int k = 0; k < KK; k++) {
            sMv[myrow][k] = vals[k];
            sMi[myrow][k] = idxs[k];
        }
    }
    __syncthreads();
    if (half == 0) {
#pragma unroll
        for (int c = 0; c < KK; c++) {
            float v = sMv[myrow][c];
            int ix = sMi[myrow][c];
            bool enter = (v < vals[KK - 1]) ||
                         (v == vals[KK - 1] && ix < idxs[KK - 1]);
            if (enter) {
                vals[KK - 1] = v;
                idxs[KK - 1] = ix;
#pragma unroll
                for (int p = KK - 1; p > 0; --p) {
                    bool s = (vals[p] < vals[p - 1]) ||
                             (vals[p] == vals[p - 1] && idxs[p] < idxs[p - 1]);
                    float va = vals[p - 1];
                    int ia = idxs[p - 1];
                    vals[p - 1] = s ? vals[p] : va;
                    idxs[p - 1] = s ? idxs[p] : ia;
                    vals[p] = s ? va : vals[p];
                    idxs[p] = s ? ia : idxs[p];
                }
            }
        }
        int base = (bm * NN + row0 + myrow) * KK;
#pragma unroll
        for (int k = 0; k < KK; k++) {
            g_idx[base + k] = idxs[k];
            atomicAdd(&g_cnt[bm * NN + idxs[k]], 1);
        }
    }
}

// ---------------- K5a: per-bm exclusive scan of counts ----------------
__global__ void __launch_bounds__(1024) k_scan() {
    int bm = blockIdx.x;
    __shared__ int s[NN];
    int t = threadIdx.x;
    int v = g_cnt[bm * NN + t];
    s[t] = v;
    __syncthreads();
    for (int off = 1; off < NN; off <<= 1) {
        int add = (t >= off) ? s[t - off] : 0;
        __syncthreads();
        s[t] += add;
        __syncthreads();
    }
    int excl = s[t] - v;
    g_start[bm * NN + t] = excl;
    g_fill[bm * NN + t] = excl;
}

// ---------------- K5b: fill CSR column lists ----------------
__global__ void k_fill() {
    int gid = blockIdx.x * blockDim.x + threadIdx.x;
    if (gid >= BMT * NN) return;
    int bm = gid >> 10;
    int n = gid & (NN - 1);
#pragma unroll
    for (int k = 0; k < KK; k++) {
        int j = g_idx[gid * KK + k];
        int pos = atomicAdd(&g_fill[bm * NN + j], 1);
        g_list[(size_t)bm * NN * KK + pos] = n;
    }
}

// ---------------- K6: edge aggregation ----------------
__global__ void __launch_bounds__(128) k_edge() {
    int j = blockIdx.x;
    int bm = blockIdx.y;
    int f = threadIdx.x;
    int cnt = g_cnt[bm * NN + j];
    int st = g_start[bm * NN + j];
    const int* lst = g_list + (size_t)bm * NN * KK + st;
    const float* Xb = g_Xs + (size_t)bm * NN * FF;
    float acc0 = 0.f, acc1 = 0.f, acc2v = 0.f, acc3 = 0.f;
    int i = 0;
    for (; i + 4 <= cnt; i += 4) {
        int n0 = lst[i], n1 = lst[i + 1], n2 = lst[i + 2], n3 = lst[i + 3];
        acc0 += Xb[(size_t)n0 * FF + f];
        acc1 += Xb[(size_t)n1 * FF + f];
        acc2v += Xb[(size_t)n2 * FF + f];
        acc3 += Xb[(size_t)n3 * FF + f];
    }
    for (; i < cnt; i++) acc0 += Xb[(size_t)lst[i] * FF + f];
    float acc = (acc0 + acc1) + (acc2v + acc3);
    float sc = (cnt > 0) ? (1.f / (float)cnt) : 0.f;
    g_tmpE[((size_t)bm * NN + j) * FF + f] = acc * sc;
}

// ---------------- K6b: cluster aggregation ----------------
__global__ void __launch_bounds__(128) k_cagg() {
    int bm = blockIdx.y;
    int base = blockIdx.x * 128;
    int f = threadIdx.x;
    __shared__ float sH[128 * NC];
    for (int t = f; t < 128 * NC; t += 128)
        sH[t] = g_Hc[((size_t)bm * NN + base) * NC + t];
    __syncthreads();
    float acc[NC] = {};
#pragma unroll 4
    for (int nn = 0; nn < 128; nn++) {
        float x = g_Xs[((size_t)bm * NN + base + nn) * FF + f];
#pragma unroll
        for (int c = 0; c < NC; c++) acc[c] = fmaf(sH[nn * NC + c], x, acc[c]);
    }
#pragma unroll
    for (int c = 0; c < NC; c++)
        atomicAdd(&g_tmpC[((size_t)bm * NC + c) * FF + f], acc[c]);
}

// ---------------- K7: final gather + cluster term + elu + output layout ----------------
__global__ void __launch_bounds__(128) k_final(float* __restrict__ out) {
    int bm = blockIdx.y;
    int base = blockIdx.x * 32;
    int f = threadIdx.x;
    __shared__ float sC[NC * FF];
    __shared__ float sH[32 * NC];
    __shared__ int sI[32 * KK];
    __shared__ float sDi[NC];
    if (f < NC) sDi[f] = 1.f / g_DeC[bm * NC + f];
    __syncthreads();
#pragma unroll
    for (int c = 0; c < NC; c++)
        sC[c * FF + f] = g_tmpC[((size_t)bm * NC + c) * FF + f] * sDi[c];
    for (int t = f; t < 32 * NC; t += 128) {
        sH[t] = g_Hc[((size_t)bm * NN + base) * NC + t];
        sI[t] = g_idx[((size_t)bm * NN + base) * KK + t];
    }
    __syncthreads();
    int b = bm >> 3, m = bm & 7;
    const float* Eb = g_tmpE + (size_t)bm * NN * FF;
#pragma unroll 4
    for (int r = 0; r < 32; r++) {
        float acc = 0.f;
#pragma unroll
        for (int k = 0; k < KK; k++) {
            int j = sI[r * KK + k];
            acc += Eb[(size_t)j * FF + f];
        }
#pragma unroll
        for (int c = 0; c < NC; c++)
            acc = fmaf(sH[r * NC + c], sC[c * FF + f], acc);
        float v = INV_SQRT11 * acc;
        v = (v > 0.f) ? v : expm1f(v);
        out[(((size_t)b * NN + base + r) * 8 + m) * FF + f] = v;
    }
}

// ---------------- launch ----------------
extern "C" void kernel_launch(void* const* d_in, const int* in_sizes, int n_in,
                              void* d_out, int out_size) {
    const float* x   = (const float*)d_in[0];  // [4,1024,8,128]
    const float* Wp  = (const float*)d_in[1];  // [64,128]
    const float* Wpb = (const float*)d_in[2];  // [64]
    const float* C   = (const float*)d_in[3];  // [10,64]
    const float* Tw  = (const float*)d_in[4];  // [128,128]
    const float* Tb  = (const float*)d_in[5];  // [128]
    float* out = (float*)d_out;

    k_gemm<<<dim3(BMT, 16, 6), 128>>>(x, Wp, Wpb, Tw, Tb);                   // 1: Zt + Xs
    k_cluster_sq<<<(BMT * NN) / 256, 256>>>(C);                              // 2: softmax+sq+zeros
    k_knn<<<dim3(NN / ROWT, BMT), 128>>>();                                  // 3: Gram + top-10 + counts
    k_scan<<<BMT, 1024>>>();                                                 // 4
    k_fill<<<(BMT * NN + 255) / 256, 256>>>();                               // 5
    k_edge<<<dim3(NN, BMT), 128>>>();                                        // 6
    k_cagg<<<dim3(NN / 128, BMT), 128>>>();                                  // 7
    k_final<<<dim3(NN / 32, BMT), 128>>>(out);                               // 8
}

// round 8
// speedup vs baseline: 1.0344x; 1.0344x over previous
#include <cuda_runtime.h>
#include <math.h>

typedef unsigned long long ull;

// Problem constants
#define BMT 32      // B*M
#define NN 1024     // nodes
#define DD 128      // input dim
#define PP 64       // projection dim
#define NC 10       // clusters
#define FF 128      // output features
#define KK 10       // k neighbors
#define INV_SQRT11 0.30151134457776363f

// kNN tiling
#define ROWT 64
#define COLT 32
#define NKP2 (PP / 4)   // 16 quads of 4 floats (2 f32x2 pairs)

// ---------------- scratch (device globals: allocation-free) ----------------
__device__ ull   g_Zt[BMT * NKP2 * NN * 2];  // Z transposed: (bm, kp2, row) -> ull2 (4 floats)
__device__ float g_sq[BMT * NN];             // squared norms
__device__ int   g_idx[BMT * NN * KK];       // knn indices
__device__ float g_Hc[BMT * NN * NC];        // cluster softmax probs
__device__ float g_Xs[BMT * NN * FF];        // X_trans * 1/sqrt(11)
__device__ int   g_cnt[BMT * NN];            // per-edge degree of H_knn
__device__ int   g_start[BMT * NN];          // CSR starts
__device__ int   g_fill[BMT * NN];           // CSR fill cursors
__device__ int   g_list[BMT * NN * KK];      // CSR column lists
__device__ float g_tmpE[BMT * NN * FF];      // De_inv * (H_knn^T @ Xs)
__device__ float g_tmpC[BMT * NC * FF];      // H_cluster^T @ Xs (unscaled)
__device__ float g_DeC[BMT * NC];            // cluster edge degrees

// ---------------- f32x2 helpers ----------------
__device__ __forceinline__ void fma2(ull& d, ull a, ull b) {
    asm("fma.rn.f32x2 %0, %1, %2, %3;" : "=l"(d) : "l"(a), "l"(b), "l"(d));
}
__device__ __forceinline__ ull pack2(float lo, float hi) {
    ull d;
    asm("mov.b64 %0, {%1, %2};" : "=l"(d) : "r"(__float_as_uint(lo)), "r"(__float_as_uint(hi)));
    return d;
}
__device__ __forceinline__ void unpack2(ull v, float& lo, float& hi) {
    unsigned a, b;
    asm("mov.b64 {%0, %1}, %2;" : "=r"(a), "=r"(b) : "l"(v));
    lo = __uint_as_float(a);
    hi = __uint_as_float(b);
}
__device__ __forceinline__ void cpa16(unsigned s, const void* g) {
    asm volatile("cp.async.cg.shared.global [%0], [%1], 16;" :: "r"(s), "l"(g));
}

// ---------------- merged GEMM: 256 thr, 64x64 tile, 4x4 thread tile --------
// z=0 -> Z (64 cols, transposed pair-packed to g_Zt)
// z=1 -> Xs cols 0-63, z=2 -> Xs cols 64-127 (row-major, scaled)
__global__ void __launch_bounds__(256) k_gemm(const float* __restrict__ X,
                                              const float* __restrict__ Wp,
                                              const float* __restrict__ Wpb,
                                              const float* __restrict__ Tw,
                                              const float* __restrict__ Tb) {
    __shared__ __align__(16) char smem_raw[32768];
    ulonglong2* sAp = (ulonglong2*)smem_raw;            // [2][8][64] = 16 KB
    ulonglong2* sWp = (ulonglong2*)(smem_raw + 16384);  // [2][8][64] = 16 KB

    int bm = blockIdx.x;
    int row0 = blockIdx.y * 64;
    int z = blockIdx.z;
    int b = bm >> 3, m = bm & 7;
    int tid = threadIdx.x;
    if (bm == 0 && blockIdx.y == 0 && z == 0) {
        for (int i = tid; i < BMT * NC; i += 256) g_DeC[i] = 0.f;
    }
    const float* Wsel = (z == 0) ? Wp : Tw;
    const float* Bsel = (z == 0) ? Wpb : Tb;
    int colbase = (z == 0) ? 0 : (z - 1) * 64;
    float scale = (z == 0) ? 1.0f : INV_SQRT11;

    const float* xbase = X + ((size_t)(b * NN) * 8 + m) * DD;
    unsigned sA_u = (unsigned)__cvta_generic_to_shared(sAp);
    unsigned sW_u = (unsigned)__cvta_generic_to_shared(sWp);

    auto issue = [&](int ch) {
        int st = ch & 1;
#pragma unroll
        for (int q = 0; q < 2; q++) {
            int e = tid + q * 256;
            int kp2 = e >> 6, r = e & 63;
            unsigned sa = sA_u + ((st * 8 + kp2) * 64 + r) * 16;
            cpa16(sa, xbase + (size_t)(row0 + r) * 1024 + ch * 32 + kp2 * 4);
            unsigned sw = sW_u + ((st * 8 + kp2) * 64 + r) * 16;
            cpa16(sw, Wsel + (size_t)(colbase + r) * DD + ch * 32 + kp2 * 4);
        }
        asm volatile("cp.async.commit_group;");
    };

    int tr = tid >> 4;  // 0..15 -> rows tr + 16*i
    int tc = tid & 15;  // 0..15 -> cols tc + 16*j

    ull acc[4][4] = {};

    issue(0);
#pragma unroll
    for (int ch = 0; ch < 4; ch++) {
        if (ch < 3) {
            issue(ch + 1);
            asm volatile("cp.async.wait_group 1;");
        } else {
            asm volatile("cp.async.wait_group 0;");
        }
        __syncthreads();
        int st = ch & 1;
#pragma unroll
        for (int kp2 = 0; kp2 < 8; kp2++) {
            const ulonglong2* ab = sAp + (st * 8 + kp2) * 64;
            const ulonglong2* wb = sWp + (st * 8 + kp2) * 64;
            ulonglong2 a0 = ab[tr + 0];
            ulonglong2 a1 = ab[tr + 16];
            ulonglong2 a2 = ab[tr + 32];
            ulonglong2 a3 = ab[tr + 48];
            ulonglong2 w0 = wb[tc + 0];
            ulonglong2 w1 = wb[tc + 16];
            ulonglong2 w2 = wb[tc + 32];
            ulonglong2 w3 = wb[tc + 48];
            fma2(acc[0][0], a0.x, w0.x); fma2(acc[0][0], a0.y, w0.y);
            fma2(acc[0][1], a0.x, w1.x); fma2(acc[0][1], a0.y, w1.y);
            fma2(acc[0][2], a0.x, w2.x); fma2(acc[0][2], a0.y, w2.y);
            fma2(acc[0][3], a0.x, w3.x); fma2(acc[0][3], a0.y, w3.y);
            fma2(acc[1][0], a1.x, w0.x); fma2(acc[1][0], a1.y, w0.y);
            fma2(acc[1][1], a1.x, w1.x); fma2(acc[1][1], a1.y, w1.y);
            fma2(acc[1][2], a1.x, w2.x); fma2(acc[1][2], a1.y, w2.y);
            fma2(acc[1][3], a1.x, w3.x); fma2(acc[1][3], a1.y, w3.y);
            fma2(acc[2][0], a2.x, w0.x); fma2(acc[2][0], a2.y, w0.y);
            fma2(acc[2][1], a2.x, w1.x); fma2(acc[2][1], a2.y, w1.y);
            fma2(acc[2][2], a2.x, w2.x); fma2(acc[2][2], a2.y, w2.y);
            fma2(acc[2][3], a2.x, w3.x); fma2(acc[2][3], a2.y, w3.y);
            fma2(acc[3][0], a3.x, w0.x); fma2(acc[3][0], a3.y, w0.y);
            fma2(acc[3][1], a3.x, w1.x); fma2(acc[3][1], a3.y, w1.y);
            fma2(acc[3][2], a3.x, w2.x); fma2(acc[3][2], a3.y, w2.y);
            fma2(acc[3][3], a3.x, w3.x); fma2(acc[3][3], a3.y, w3.y);
        }
        __syncthreads();
    }

    float bv[4];
#pragma unroll
    for (int j = 0; j < 4; j++) bv[j] = Bsel[colbase + tc + 16 * j];

    if (z >= 1) {
#pragma unroll
        for (int i = 0; i < 4; i++) {
            int n = row0 + tr + 16 * i;
            float* op = g_Xs + ((size_t)bm * NN + n) * FF + colbase;
#pragma unroll
            for (int j = 0; j < 4; j++) {
                float lo, hi;
                unpack2(acc[i][j], lo, hi);
                op[tc + 16 * j] = (lo + hi + bv[j]) * scale;
            }
        }
    } else {
        // transpose epilogue into g_Zt; sT[col][row], 66-float pad
        float* sT = (float*)smem_raw;  // 64*66*4 = 16.9 KB
        __syncthreads();
#pragma unroll
        for (int i = 0; i < 4; i++) {
            int r = tr + 16 * i;
#pragma unroll
            for (int j = 0; j < 4; j++) {
                float lo, hi;
                unpack2(acc[i][j], lo, hi);
                sT[(tc + 16 * j) * 66 + r] = lo + hi + bv[j];
            }
        }
        __syncthreads();
        ulonglong2* zt2 = (ulonglong2*)g_Zt;
#pragma unroll
        for (int q = 0; q < 4; q++) {
            int e = tid + q * 256;
            int kp2l = e >> 6, r = e & 63;
            float z0 = sT[(kp2l * 4 + 0) * 66 + r];
            float z1 = sT[(kp2l * 4 + 1) * 66 + r];
            float z2 = sT[(kp2l * 4 + 2) * 66 + r];
            float z3 = sT[(kp2l * 4 + 3) * 66 + r];
            ulonglong2 v;
            v.x = pack2(z0, z1);
            v.y = pack2(z2, z3);
            zt2[((size_t)(bm * NKP2 + kp2l)) * NN + row0 + r] = v;
        }
    }
}

// ---------------- K_cluster_sq: softmax + DeC + sq norm + zero cnt/tmpC ----
__global__ void __launch_bounds__(256) k_cluster_sq(const float* __restrict__ C) {
    __shared__ float sC[NC * PP];
    __shared__ float sDeC[NC];
    int tid = threadIdx.x;
    for (int t = tid; t < NC * PP; t += 256) sC[t] = C[t];
    if (tid < NC) sDeC[tid] = 0.f;
    __syncthreads();
    int row = blockIdx.x * 256 + tid;
    int bm = row >> 10;
    int n = row & (NN - 1);
    g_cnt[row] = 0;
    for (int i = row; i < BMT * NC * FF; i += BMT * NN) g_tmpC[i] = 0.f;
    const ulonglong2* zt2 = (const ulonglong2*)g_Zt;
    float acc[NC] = {};
    float sq = 0.f;
#pragma unroll
    for (int kp2 = 0; kp2 < NKP2; kp2++) {
        ulonglong2 v = zt2[((size_t)(bm * NKP2 + kp2)) * NN + n];
        float z0, z1, z2, z3;
        unpack2(v.x, z0, z1);
        unpack2(v.y, z2, z3);
        sq = fmaf(z0, z0, fmaf(z1, z1, fmaf(z2, z2, fmaf(z3, z3, sq))));
        const float* cp = &sC[kp2 * 4];
#pragma unroll
        for (int c = 0; c < NC; c++) {
            acc[c] = fmaf(z0, cp[c * PP + 0], acc[c]);
            acc[c] = fmaf(z1, cp[c * PP + 1], acc[c]);
            acc[c] = fmaf(z2, cp[c * PP + 2], acc[c]);
            acc[c] = fmaf(z3, cp[c * PP + 3], acc[c]);
        }
    }
    g_sq[row] = sq;
    float mx = acc[0];
#pragma unroll
    for (int c = 1; c < NC; c++) mx = fmaxf(mx, acc[c]);
    float p[NC], sum = 0.f;
#pragma unroll
    for (int c = 0; c < NC; c++) {
        p[c] = expf(acc[c] - mx);
        sum += p[c];
    }
    float inv = 1.f / sum;
#pragma unroll
    for (int c = 0; c < NC; c++) {
        p[c] *= inv;
        g_Hc[(size_t)row * NC + c] = p[c];
    }
#pragma unroll
    for (int c = 0; c < NC; c++)
#pragma unroll
        for (int o = 16; o; o >>= 1) p[c] += __shfl_xor_sync(0xffffffffu, p[c], o);
    if ((tid & 31) == 0) {
#pragma unroll
        for (int c = 0; c < NC; c++) atomicAdd(&sDeC[c], p[c]);
    }
    __syncthreads();
    if (tid < NC) atomicAdd(&g_DeC[bm * NC + tid], sDeC[tid]);
}

// ---------------- K2: FMA2-bound Gram tiles + in-kernel top-10 ----------------
__global__ void __launch_bounds__(128) k_knn() {
    int bm = blockIdx.y;
    int row0 = blockIdx.x * ROWT;

    __shared__ __align__(16) ulonglong2 sQ[NKP2][ROWT];  // 16KB
    __shared__ __align__(16) ulonglong2 sK[NKP2][COLT];  // 8KB
    __shared__ float sD[COLT][ROWT + 2];                 // 8.25KB
    __shared__ float ssq[COLT];
    __shared__ float sMv[ROWT][KK];
    __shared__ int   sMi[ROWT][KK];

    const ulonglong2* zt2 = (const ulonglong2*)g_Zt + (size_t)bm * NKP2 * NN;
    int tid = threadIdx.x;

#pragma unroll
    for (int e = tid; e < NKP2 * ROWT; e += 128) {
        int kp2 = e >> 6, r = e & 63;
        sQ[kp2][r] = zt2[(size_t)kp2 * NN + row0 + r];
    }

    int tr = tid >> 3;
    int tc = tid & 7;
    int myrow = tid & 63;
    int half = tid >> 6;

    float vals[KK];
    int idxs[KK];
#pragma unroll
    for (int k = 0; k < KK; k++) {
        vals[k] = __int_as_float(0x7f800000);
        idxs[k] = 0x7fffffff;
    }

    for (int j0 = 0; j0 < NN; j0 += COLT) {
#pragma unroll
        for (int e = tid; e < NKP2 * COLT; e += 128) {
            int kp2 = e >> 5, r = e & 31;
            sK[kp2][r] = zt2[(size_t)kp2 * NN + j0 + r];
        }
        if (tid < COLT) ssq[tid] = g_sq[bm * NN + j0 + tid];
        __syncthreads();

        ull acc[4][4] = {};
#pragma unroll
        for (int kp2 = 0; kp2 < NKP2; kp2++) {
            ulonglong2 q0 = sQ[kp2][tr + 0];
            ulonglong2 q1 = sQ[kp2][tr + 16];
            ulonglong2 q2 = sQ[kp2][tr + 32];
            ulonglong2 q3 = sQ[kp2][tr + 48];
            ulonglong2 c0 = sK[kp2][tc + 0];
            ulonglong2 c1 = sK[kp2][tc + 8];
            ulonglong2 c2 = sK[kp2][tc + 16];
            ulonglong2 c3 = sK[kp2][tc + 24];
            fma2(acc[0][0], q0.x, c0.x); fma2(acc[0][0], q0.y, c0.y);
            fma2(acc[0][1], q0.x, c1.x); fma2(acc[0][1], q0.y, c1.y);
            fma2(acc[0][2], q0.x, c2.x); fma2(acc[0][2], q0.y, c2.y);
            fma2(acc[0][3], q0.x, c3.x); fma2(acc[0][3], q0.y, c3.y);
            fma2(acc[1][0], q1.x, c0.x); fma2(acc[1][0], q1.y, c0.y);
            fma2(acc[1][1], q1.x, c1.x); fma2(acc[1][1], q1.y, c1.y);
            fma2(acc[1][2], q1.x, c2.x); fma2(acc[1][2], q1.y, c2.y);
            fma2(acc[1][3], q1.x, c3.x); fma2(acc[1][3], q1.y, c3.y);
            fma2(acc[2][0], q2.x, c0.x); fma2(acc[2][0], q2.y, c0.y);
            fma2(acc[2][1], q2.x, c1.x); fma2(acc[2][1], q2.y, c1.y);
            fma2(acc[2][2], q2.x, c2.x); fma2(acc[2][2], q2.y, c2.y);
            fma2(acc[2][3], q2.x, c3.x); fma2(acc[2][3], q2.y, c3.y);
            fma2(acc[3][0], q3.x, c0.x); fma2(acc[3][0], q3.y, c0.y);
            fma2(acc[3][1], q3.x, c1.x); fma2(acc[3][1], q3.y, c1.y);
            fma2(acc[3][2], q3.x, c2.x); fma2(acc[3][2], q3.y, c2.y);
            fma2(acc[3][3], q3.x, c3.x); fma2(acc[3][3], q3.y, c3.y);
        }
#pragma unroll
        for (int i = 0; i < 4; i++) {
#pragma unroll
            for (int j = 0; j < 4; j++) {
                float lo, hi;
                unpack2(acc[i][j], lo, hi);
                int col = tc + 8 * j;
                sD[col][tr + 16 * i] = fmaf(-2.f, lo + hi, ssq[col]);
            }
        }
        __syncthreads();

        int cb = half * 16;
#pragma unroll
        for (int cc = 0; cc < 16; cc++) {
            float d2 = sD[cb + cc][myrow];
            if (d2 < vals[KK - 1]) {
                vals[KK - 1] = d2;
                idxs[KK - 1] = j0 + cb + cc;
#pragma unroll
                for (int p = KK - 1; p > 0; --p) {
                    bool s = vals[p] < vals[p - 1];
                    float va = vals[p - 1];
                    int ia = idxs[p - 1];
                    vals[p - 1] = s ? vals[p] : va;
                    idxs[p - 1] = s ? idxs[p] : ia;
                    vals[p] = s ? va : vals[p];
                    idxs[p] = s ? ia : idxs[p];
                }
            }
        }
        __syncthreads();
    }

    if (half == 1) {
#pragma unroll
        for (int k = 0; k < KK; k++) {
            sMv[myrow][k] = vals[k];
            sMi[myrow][k] = idxs[k];
        }
    }
    __syncthreads();
    if (half == 0) {
#pragma unroll
        for (int c = 0; c < KK; c++) {
            float v = sMv[myrow][c];
            int ix = sMi[myrow][c];
            bool enter = (v < vals[KK - 1]) ||
                         (v == vals[KK - 1] && ix < idxs[KK - 1]);
            if (enter) {
                vals[KK - 1] = v;
                idxs[KK - 1] = ix;
#pragma unroll
                for (int p = KK - 1; p > 0; --p) {
                    bool s = (vals[p] < vals[p - 1]) ||
                             (vals[p] == vals[p - 1] && idxs[p] < idxs[p - 1]);
                    float va = vals[p - 1];
                    int ia = idxs[p - 1];
                    vals[p - 1] = s ? vals[p] : va;
                    idxs[p - 1] = s ? idxs[p] : ia;
                    vals[p] = s ? va : vals[p];
                    idxs[p] = s ? ia : idxs[p];
                }
            }
        }
        int base = (bm * NN + row0 + myrow) * KK;
#pragma unroll
        for (int k = 0; k < KK; k++) {
            g_idx[base + k] = idxs[k];
            atomicAdd(&g_cnt[bm * NN + idxs[k]], 1);
        }
    }
}

// ---------------- K5a: per-bm exclusive scan of counts ----------------
__global__ void __launch_bounds__(1024) k_scan() {
    int bm = blockIdx.x;
    __shared__ int s[NN];
    int t = threadIdx.x;
    int v = g_cnt[bm * NN + t];
    s[t] = v;
    __syncthreads();
    for (int off = 1; off < NN; off <<= 1) {
        int add = (t >= off) ? s[t - off] : 0;
        __syncthreads();
        s[t] += add;
        __syncthreads();
    }
    int excl = s[t] - v;
    g_start[bm * NN + t] = excl;
    g_fill[bm * NN + t] = excl;
}

// ---------------- K5b: fill CSR column lists ----------------
__global__ void k_fill() {
    int gid = blockIdx.x * blockDim.x + threadIdx.x;
    if (gid >= BMT * NN) return;
    int bm = gid >> 10;
    int n = gid & (NN - 1);
#pragma unroll
    for (int k = 0; k < KK; k++) {
        int j = g_idx[gid * KK + k];
        int pos = atomicAdd(&g_fill[bm * NN + j], 1);
        g_list[(size_t)bm * NN * KK + pos] = n;
    }
}

// ---------------- K6: edge aggregation (2 edges per block) ----------------
__global__ void __launch_bounds__(256) k_edge() {
    int j = blockIdx.x * 2 + (threadIdx.x >> 7);
    int bm = blockIdx.y;
    int f = threadIdx.x & 127;
    int cnt = g_cnt[bm * NN + j];
    int st = g_start[bm * NN + j];
    const int* lst = g_list + (size_t)bm * NN * KK + st;
    const float* Xb = g_Xs + (size_t)bm * NN * FF;
    float acc0 = 0.f, acc1 = 0.f, acc2v = 0.f, acc3 = 0.f;
    int i = 0;
    for (; i + 4 <= cnt; i += 4) {
        int n0 = lst[i], n1 = lst[i + 1], n2 = lst[i + 2], n3 = lst[i + 3];
        acc0 += Xb[(size_t)n0 * FF + f];
        acc1 += Xb[(size_t)n1 * FF + f];
        acc2v += Xb[(size_t)n2 * FF + f];
        acc3 += Xb[(size_t)n3 * FF + f];
    }
    for (; i < cnt; i++) acc0 += Xb[(size_t)lst[i] * FF + f];
    float acc = (acc0 + acc1) + (acc2v + acc3);
    float sc = (cnt > 0) ? (1.f / (float)cnt) : 0.f;
    g_tmpE[((size_t)bm * NN + j) * FF + f] = acc * sc;
}

// ---------------- K6b: cluster aggregation ----------------
__global__ void __launch_bounds__(128) k_cagg() {
    int bm = blockIdx.y;
    int base = blockIdx.x * 128;
    int f = threadIdx.x;
    __shared__ float sH[128 * NC];
    for (int t = f; t < 128 * NC; t += 128)
        sH[t] = g_Hc[((size_t)bm * NN + base) * NC + t];
    __syncthreads();
    float acc[NC] = {};
#pragma unroll 4
    for (int nn = 0; nn < 128; nn++) {
        float x = g_Xs[((size_t)bm * NN + base + nn) * FF + f];
#pragma unroll
        for (int c = 0; c < NC; c++) acc[c] = fmaf(sH[nn * NC + c], x, acc[c]);
    }
#pragma unroll
    for (int c = 0; c < NC; c++)
        atomicAdd(&g_tmpC[((size_t)bm * NC + c) * FF + f], acc[c]);
}

// ---------------- K7: final gather + cluster term + elu + output layout ----------------
__global__ void __launch_bounds__(128) k_final(float* __restrict__ out) {
    int bm = blockIdx.y;
    int base = blockIdx.x * 32;
    int f = threadIdx.x;
    __shared__ float sC[NC * FF];
    __shared__ float sH[32 * NC];
    __shared__ int sI[32 * KK];
    __shared__ float sDi[NC];
    if (f < NC) sDi[f] = 1.f / g_DeC[bm * NC + f];
    __syncthreads();
#pragma unroll
    for (int c = 0; c < NC; c++)
        sC[c * FF + f] = g_tmpC[((size_t)bm * NC + c) * FF + f] * sDi[c];
    for (int t = f; t < 32 * NC; t += 128) {
        sH[t] = g_Hc[((size_t)bm * NN + base) * NC + t];
        sI[t] = g_idx[((size_t)bm * NN + base) * KK + t];
    }
    __syncthreads();
    int b = bm >> 3, m = bm & 7;
    const float* Eb = g_tmpE + (size_t)bm * NN * FF;
#pragma unroll 4
    for (int r = 0; r < 32; r++) {
        float acc = 0.f;
#pragma unroll
        for (int k = 0; k < KK; k++) {
            int j = sI[r * KK + k];
            acc += Eb[(size_t)j * FF + f];
        }
#pragma unroll
        for (int c = 0; c < NC; c++)
            acc = fmaf(sH[r * NC + c], sC[c * FF + f], acc);
        float v = INV_SQRT11 * acc;
        v = (v > 0.f) ? v : expm1f(v);
        out[(((size_t)b * NN + base + r) * 8 + m) * FF + f] = v;
    }
}

// ---------------- launch ----------------
extern "C" void kernel_launch(void* const* d_in, const int* in_sizes, int n_in,
                              void* d_out, int out_size) {
    const float* x   = (const float*)d_in[0];  // [4,1024,8,128]
    const float* Wp  = (const float*)d_in[1];  // [64,128]
    const float* Wpb = (const float*)d_in[2];  // [64]
    const float* C   = (const float*)d_in[3];  // [10,64]
    const float* Tw  = (const float*)d_in[4];  // [128,128]
    const float* Tb  = (const float*)d_in[5];  // [128]
    float* out = (float*)d_out;

    k_gemm<<<dim3(BMT, 16, 3), 256>>>(x, Wp, Wpb, Tw, Tb);                   // 1: Zt + Xs
    k_cluster_sq<<<(BMT * NN) / 256, 256>>>(C);                              // 2: softmax+sq+zeros
    k_knn<<<dim3(NN / ROWT, BMT), 128>>>();                                  // 3: Gram + top-10 + counts
    k_scan<<<BMT, 1024>>>();                                                 // 4
    k_fill<<<(BMT * NN + 255) / 256, 256>>>();                               // 5
    k_edge<<<dim3(NN / 2, BMT), 256>>>();                                    // 6
    k_cagg<<<dim3(NN / 128, BMT), 128>>>();                                  // 7
    k_final<<<dim3(NN / 32, BMT), 128>>>(out);                               // 8
}